// round 5
// baseline (speedup 1.0000x reference)
#include <cuda_runtime.h>
#include <math.h>

#define CC 128
#define HS 64
#define LL 4096
#define ND 2048   // CC*16
#define NB 2
#define LCH 16        // l-chunk per stencil block
#define NCH (LL/LCH)  // 256 chunks
#define CAPC 16       // per-chunk survivor list (cannot overflow: 16 l per chunk)
#define CAPF 64       // final compact list per column

// ---------------- device scratch (module-scope, no runtime alloc) -------------
__device__ float g_fds[NB * CC * LL];
__device__ float g_bds[NB * CC * LL];
__device__ float g_S[NB * LL];
__device__ float g_inorm[NB * LL];
__device__ float g_mm[LL];
__device__ float g_bufA[(size_t)NB * LL * LL];   // G
__device__ float g_bufB[(size_t)NB * LL * LL];   // yscore
__device__ float g_hmax[(size_t)NB * NCH * LL];
__device__ float g_hsum[(size_t)NB * NCH * LL];
__device__ int   g_hcnt[(size_t)NB * NCH * LL];
__device__ int   g_sidx[(size_t)NB * NCH * LL * CAPC];
__device__ float g_sval[(size_t)NB * NCH * LL * CAPC];
__device__ int   g_ccnt[NB * LL];
__device__ int   g_cidx[(size_t)NB * LL * CAPF];
__device__ float g_cval[(size_t)NB * LL * CAPF];
__device__ float g_rinv[NB * LL];
__device__ float g_wmat[(size_t)NB * LL * ND];
__device__ float g_v[(size_t)NB * LL * ND];

// ---------------- small kernels ----------------------------------------------
__global__ void k_downsample(const float* __restrict__ f, const float* __restrict__ b) {
    int idx = blockIdx.x * 256 + threadIdx.x;           // NB*CC*64*64
    int j = idx & 63, i = (idx >> 6) & 63;
    int c = (idx >> 12) & 127, bb = idx >> 19;
    size_t src = ((size_t)(bb * CC + c) * 128 + 2 * i) * 128 + 2 * j;
    g_fds[idx] = f[src];
    g_bds[idx] = b[src];
}

__global__ void k_stats() {                              // S[b][l] = sum_c bds^2
    int idx = blockIdx.x * 256 + threadIdx.x;            // NB*LL
    int bb = idx >> 12; int l = idx & 4095;
    float acc = 0.f;
    for (int c = 0; c < CC; c++) {
        float v = g_bds[((size_t)bb * CC + c) * LL + l];
        acc = fmaf(v, v, acc);
    }
    g_S[idx] = acc;
}

__global__ void k_normmm(const float* __restrict__ mask) {
    int idx = blockIdx.x * 256 + threadIdx.x;            // NB*LL
    int bb = idx >> 12; int l = idx & 4095;
    int i = l >> 6, j = l & 63;
    float acc = 0.1152f;                                 // 1152 * 1e-4
    float msum = 0.f;
    for (int du = -1; du <= 1; du++)
        for (int dv = -1; dv <= 1; dv++) {
            int ii = i + du, jj = j + dv;
            if (ii >= 0 && ii < 64 && jj >= 0 && jj < 64) {
                acc += g_S[bb * LL + ii * 64 + jj];
                if (bb == 0) msum += mask[(2 * ii) * 128 + 2 * jj];
            }
        }
    g_inorm[idx] = rsqrtf(acc);
    if (bb == 0) g_mm[l] = (msum == 0.f) ? 1.f : 0.f;
}

// ---------------- packed f32x2 SGEMM (Gram): G[l][p] = sum_c bds[c][l]*fds[c][p]
#define BM 128
#define BN 128
#define BKK 16

__device__ __forceinline__ unsigned long long dup2(float x) {
    unsigned long long r;
    asm("mov.b64 %0, {%1, %2};" : "=l"(r) : "f"(x), "f"(x));
    return r;
}
__device__ __forceinline__ void ffma2(unsigned long long& d, unsigned long long a, unsigned long long b) {
    asm("fma.rn.f32x2 %0, %1, %2, %0;" : "+l"(d) : "l"(a), "l"(b));
}

__global__ __launch_bounds__(256, 2)
void gemm_gram() {
    const int M = LL, N = LL, K = CC;
    const float* A = g_bds; const float* Bm = g_fds; float* Cm = g_bufA;
    __shared__ float As[BKK][BM];
    __shared__ float Bs[BKK][BN];
    const int tid = threadIdx.x;
    const int m0 = blockIdx.y * BM, n0 = blockIdx.x * BN;
    const int z = blockIdx.z;
    A += (size_t)z * CC * LL; Bm += (size_t)z * CC * LL; Cm += (size_t)z * LL * LL;

    int lk[2], lm4[2];
#pragma unroll
    for (int r = 0; r < 2; r++) {
        int idx = tid + r * 256;
        lk[r] = idx >> 5;
        lm4[r] = (idx & 31) << 2;
    }

    unsigned long long acc[4][8];
#pragma unroll
    for (int a = 0; a < 4; a++)
#pragma unroll
        for (int b = 0; b < 8; b++) acc[a][b] = 0ull;

    const int ty = tid >> 4, tx = tid & 15;

    for (int k0 = 0; k0 < K; k0 += BKK) {
#pragma unroll
        for (int r = 0; r < 2; r++) {
            *(float4*)&As[lk[r]][lm4[r]] = *(const float4*)&A[(size_t)(k0 + lk[r]) * M + m0 + lm4[r]];
            *(float4*)&Bs[lk[r]][lm4[r]] = *(const float4*)&Bm[(size_t)(k0 + lk[r]) * N + n0 + lm4[r]];
        }
        __syncthreads();
#pragma unroll
        for (int kk = 0; kk < BKK; kk++) {
            const ulonglong2* A2 = (const ulonglong2*)&As[kk][0];
            ulonglong2 av0 = A2[ty];
            ulonglong2 av1 = A2[16 + ty];
            unsigned long long ap[4] = {av0.x, av0.y, av1.x, av1.y};
            const float4* B4 = (const float4*)&Bs[kk][0];
            float4 bv0 = B4[tx], bv1 = B4[16 + tx];
            unsigned long long bd[8] = {dup2(bv0.x), dup2(bv0.y), dup2(bv0.z), dup2(bv0.w),
                                        dup2(bv1.x), dup2(bv1.y), dup2(bv1.z), dup2(bv1.w)};
#pragma unroll
            for (int a = 0; a < 4; a++)
#pragma unroll
                for (int bj = 0; bj < 8; bj++) ffma2(acc[a][bj], ap[a], bd[bj]);
        }
        __syncthreads();
    }

    union UF { unsigned long long u; float2 f; };
#pragma unroll
    for (int a = 0; a < 4; a++) {
        int mrow = m0 + ((a & 2) ? 64 : 0) + ty * 4 + (a & 1) * 2;
        UF u0, u1, u2, u3;
        u0.u = acc[a][0]; u1.u = acc[a][1]; u2.u = acc[a][2]; u3.u = acc[a][3];
        float4 lo0 = make_float4(u0.f.x, u1.f.x, u2.f.x, u3.f.x);
        float4 hi0 = make_float4(u0.f.y, u1.f.y, u2.f.y, u3.f.y);
        u0.u = acc[a][4]; u1.u = acc[a][5]; u2.u = acc[a][6]; u3.u = acc[a][7];
        float4 lo1 = make_float4(u0.f.x, u1.f.x, u2.f.x, u3.f.x);
        float4 hi1 = make_float4(u0.f.y, u1.f.y, u2.f.y, u3.f.y);
        float* c0 = &Cm[(size_t)mrow * N + n0 + tx * 4];
        *(float4*)c0 = lo0;
        *(float4*)(c0 + 64) = lo1;
        float* c1 = &Cm[(size_t)(mrow + 1) * N + n0 + tx * 4];
        *(float4*)c1 = hi0;
        *(float4*)(c1 + 64) = hi1;
    }
}

// -------- diagonal-shift sum of Gram + normalization: G(bufA) -> y(bufB) -----
__global__ void k_diagsum() {
    int q = blockIdx.y * 256 + threadIdx.x;
    int r0 = blockIdx.x * LCH;
    int bb = blockIdx.z;
    int pi = q >> 6, pj = q & 63;
    const float* G = g_bufA + (size_t)bb * LL * LL;
    float* Y = g_bufB + (size_t)bb * LL * LL;
    bool qok[3][3]; int qoff[3][3];
#pragma unroll
    for (int du = -1; du <= 1; du++)
#pragma unroll
        for (int dv = -1; dv <= 1; dv++) {
            qok[du + 1][dv + 1] = ((unsigned)(pi + du) < 64u && (unsigned)(pj + dv) < 64u);
            qoff[du + 1][dv + 1] = q + du * 64 + dv;
        }
    for (int rr = 0; rr < LCH; rr++) {
        int r = r0 + rr;
        int i = r >> 6, j = r & 63;
        float acc = 0.f;
#pragma unroll
        for (int du = -1; du <= 1; du++)
#pragma unroll
            for (int dv = -1; dv <= 1; dv++) {
                if (qok[du + 1][dv + 1] &&
                    (unsigned)(i + du) < 64u && (unsigned)(j + dv) < 64u)
                    acc += G[(size_t)(r + du * 64 + dv) * LL + qoff[du + 1][dv + 1]];
            }
        Y[(size_t)r * LL + q] = acc * g_inorm[bb * LL + r];
    }
}

// -------- fused fuse1+fuse2 stencil -> logits in regs -> chunk select --------
__device__ __forceinline__ int Tsw(int x) { return ((x & 63) << 6) | (x >> 6); }

__global__ void k_logsel() {
    int p = blockIdx.y * 256 + threadIdx.x;
    int l0 = blockIdx.x * LCH;
    int bb = blockIdx.z;
    const float* Y = g_bufB + (size_t)bb * LL * LL;
    int q2 = Tsw(p);
    bool cok[3]; int cbase[3];
#pragma unroll
    for (int d2 = -1; d2 <= 1; d2++) {
        int qq = q2 + d2;
        cok[d2 + 1] = ((unsigned)qq < (unsigned)LL);
        cbase[d2 + 1] = cok[d2 + 1] ? Tsw(qq) : 0;
    }
    float lg[LCH];
    float mx = -1e30f;
#pragma unroll 4
    for (int ll = 0; ll < LCH; ll++) {
        int l = l0 + ll;
        int r2 = Tsw(l);
        float acc = 0.f;
#pragma unroll
        for (int d2 = -1; d2 <= 1; d2++) {
            int rr = r2 + d2;
            if (!cok[d2 + 1] || (unsigned)rr >= (unsigned)LL) continue;
            int a2 = Tsw(rr);
            int b2 = cbase[d2 + 1];
#pragma unroll
            for (int d1 = -1; d1 <= 1; d1++) {
                int aa = a2 + d1, bq = b2 + d1;
                if ((unsigned)aa < (unsigned)LL && (unsigned)bq < (unsigned)LL)
                    acc += Y[(size_t)aa * LL + bq];
            }
        }
        float v = acc * (g_mm[l] * 10.f);
        lg[ll] = v;
        mx = fmaxf(mx, v);
    }
    size_t hidx = ((size_t)bb * NCH + blockIdx.x) * LL + p;
    float s = 0.f;
    int cnt = 0;
    size_t base = hidx * CAPC;
    float thr = mx - 25.f;
#pragma unroll 4
    for (int ll = 0; ll < LCH; ll++) {
        float e = __expf(lg[ll] - mx);
        s += e;
        if (lg[ll] > thr && g_mm[l0 + ll] > 0.f) {
            g_sidx[base + cnt] = l0 + ll;
            g_sval[base + cnt] = e;
            cnt++;
        }
    }
    g_hmax[hidx] = mx;
    g_hsum[hidx] = s;
    g_hcnt[hidx] = cnt;
}

// -------- merge chunk records: global max, exact denominator, compact list ---
__global__ void k_merge() {
    int p = blockIdx.x * 256 + threadIdx.x;
    int bb = blockIdx.y;
    float gmax = -1e30f;
    for (int c = 0; c < NCH; c++)
        gmax = fmaxf(gmax, g_hmax[((size_t)bb * NCH + c) * LL + p]);
    float s = 0.f;
    int cnt = 0;
    size_t cbase = (size_t)(bb * LL + p) * CAPF;
    float thr = gmax - 25.f;
    for (int c = 0; c < NCH; c++) {
        size_t hidx = ((size_t)bb * NCH + c) * LL + p;
        float hm = g_hmax[hidx];
        float sc = __expf(hm - gmax);
        s += g_hsum[hidx] * sc;
        if (hm > thr) {
            int hc = g_hcnt[hidx];
            size_t ebase = hidx * CAPC;
            for (int i = 0; i < hc && cnt < CAPF; i++) {
                g_cidx[cbase + cnt] = g_sidx[ebase + i];
                g_cval[cbase + cnt] = g_sval[ebase + i] * sc;
                cnt++;
            }
        }
    }
    g_ccnt[bb * LL + p] = cnt;
    g_rinv[bb * LL + p] = 1.f / s;
}

// -------- pack raw 4x4 patches of b: W[b][l][c*16+kh*4+kw] -------------------
__global__ void k_packw(const float* __restrict__ b) {
    int idx = blockIdx.x * 256 + threadIdx.x;            // NB*LL*ND
    int n = idx & 2047, l = (idx >> 11) & 4095, bb = idx >> 23;
    int kw = n & 3, kh = (n >> 2) & 3, c = n >> 4;
    int li = l >> 6, lj = l & 63;
    int row = 2 * li - 1 + kh, col = 2 * lj - 1 + kw;
    float v = 0.f;
    if ((unsigned)row < 128u && (unsigned)col < 128u)
        v = b[((size_t)(bb * CC + c) * 128 + row) * 128 + col];
    g_wmat[idx] = v;
}

// -------- sparse attn @ W: g_v[p][n] = sum_{selected l} e * W[l][n] ----------
__global__ __launch_bounds__(256, 4)
void k_spmm() {
    int p = blockIdx.x, bb = blockIdx.y;
    int tid = threadIdx.x;
    int cnt = g_ccnt[bb * LL + p];
    size_t base = (size_t)(bb * LL + p) * CAPF;
    const float* W = g_wmat + (size_t)bb * LL * ND;
    float4 a0 = make_float4(0.f, 0.f, 0.f, 0.f);
    float4 a1 = make_float4(0.f, 0.f, 0.f, 0.f);
    for (int i = 0; i < cnt; i++) {
        int l = g_cidx[base + i];
        float e = g_cval[base + i];
        const float4* w = (const float4*)(W + (size_t)l * ND);
        float4 w0 = w[tid], w1 = w[tid + 256];
        a0.x = fmaf(e, w0.x, a0.x); a0.y = fmaf(e, w0.y, a0.y);
        a0.z = fmaf(e, w0.z, a0.z); a0.w = fmaf(e, w0.w, a0.w);
        a1.x = fmaf(e, w1.x, a1.x); a1.y = fmaf(e, w1.y, a1.y);
        a1.z = fmaf(e, w1.z, a1.z); a1.w = fmaf(e, w1.w, a1.w);
    }
    float4* out = (float4*)(g_v + (size_t)(bb * LL + p) * ND);
    out[tid] = a0;
    out[tid + 256] = a1;
}

// -------- smem-staged gather: out[bb][c][oh][ow], rinv & /4 folded -----------
__global__ __launch_bounds__(256, 4)
void k_gather(float* __restrict__ out) {
    __shared__ float sm[256][17];                        // [cl*128 + p_local][k]
    int cpair = blockIdx.x;                              // 0..63
    int oh = blockIdx.y;
    int bb = blockIdx.z;
    int tid = threadIdx.x;
    const float* P = g_v + (size_t)bb * LL * ND;
    const float* rin = g_rinv + bb * LL;

    int p0 = (oh + 1) & 1;                               // kh parity
    int ih_hi = (oh + 1 - p0) >> 1;                      // for kh = p0
    int ih_lo = ih_hi - 1;                               // for kh = p0+2

    // load: seg = tid -> (cl, ihsel, iw); 16 floats each
    {
        int cl = tid >> 7;
        int p_local = tid & 127;
        int ihsel = p_local >> 6, iw = p_local & 63;
        int ih = ihsel ? ih_hi : ih_lo;
        int c = cpair * 2 + cl;
        if ((unsigned)ih < 64u) {
            int pp = ih * 64 + iw;
            float rv = rin[pp];
            const float4* src = (const float4*)(P + (size_t)pp * ND + c * 16);
#pragma unroll
            for (int v4 = 0; v4 < 4; v4++) {
                float4 w = src[v4];
                sm[tid][v4 * 4 + 0] = w.x * rv;
                sm[tid][v4 * 4 + 1] = w.y * rv;
                sm[tid][v4 * 4 + 2] = w.z * rv;
                sm[tid][v4 * 4 + 3] = w.w * rv;
            }
        } else {
#pragma unroll
            for (int k = 0; k < 16; k++) sm[tid][k] = 0.f;
        }
    }
    __syncthreads();

    // compute: thread -> (cl, ow)
    int cl = tid >> 7;
    int ow = tid & 127;
    int q0 = (ow + 1) & 1;
    int iwH = (ow + 1 - q0) >> 1;                        // for kw = q0
    int iwL = iwH - 1;                                   // for kw = q0+2
    float acc = 0.f;
#pragma unroll
    for (int a = 0; a < 2; a++) {                        // kh sel: a=0 -> kh=p0 (ih_hi), a=1 -> kh=p0+2 (ih_lo)
        int kh = p0 + 2 * a;
        int ihsel = a ? 0 : 1;
#pragma unroll
        for (int bq = 0; bq < 2; bq++) {                 // kw sel
            int kw = q0 + 2 * bq;
            int iw = bq ? iwL : iwH;
            if ((unsigned)iw < 64u)
                acc += sm[cl * 128 + ihsel * 64 + iw][kh * 4 + kw];
        }
    }
    int c = cpair * 2 + cl;
    out[(((size_t)bb * CC + c) * 128 + oh) * 128 + ow] = acc * 0.25f;
}

// ---------------- launch -----------------------------------------------------
extern "C" void kernel_launch(void* const* d_in, const int* in_sizes, int n_in,
                              void* d_out, int out_size) {
    const float* f = (const float*)d_in[0];
    const float* b = (const float*)d_in[1];
    const float* mask = (const float*)d_in[2];
    float* out = (float*)d_out;

    k_downsample<<<4096, 256>>>(f, b);
    k_stats<<<32, 256>>>();
    k_normmm<<<32, 256>>>(mask);
    gemm_gram<<<dim3(32, 32, NB), 256>>>();
    k_diagsum<<<dim3(NCH, 16, NB), 256>>>();
    k_logsel<<<dim3(NCH, 16, NB), 256>>>();
    k_merge<<<dim3(16, NB), 256>>>();
    k_packw<<<65536, 256>>>(b);
    k_spmm<<<dim3(4096, NB), 256>>>();
    k_gather<<<dim3(64, 128, NB), 256>>>(out);
}

// round 9
// speedup vs baseline: 1.1023x; 1.1023x over previous
#include <cuda_runtime.h>
#include <math.h>

#define CC 128
#define HS 64
#define LL 4096
#define ND 2048   // CC*16
#define NB 2
#define LCH 16        // l-chunk per stencil block
#define NCH (LL/LCH)  // 256 chunks
#define CAPC 16       // per-chunk survivor list (cannot overflow: 16 l per chunk)
#define NSC 16        // super-chunks (16 chunks each)
#define CAPF 64       // final compact list per column
#define OHB 4         // oh rows per gather block

// ---------------- device scratch (module-scope, no runtime alloc) -------------
__device__ float g_fds[NB * CC * LL];
__device__ float g_bds[NB * CC * LL];
__device__ float g_S[NB * LL];
__device__ float g_inorm[NB * LL];
__device__ float g_mm[LL];
__device__ float g_bufA[(size_t)NB * LL * LL];   // G
__device__ float g_bufB[(size_t)NB * LL * LL];   // yscore
__device__ float g_hmax[(size_t)NB * NCH * LL];
__device__ float g_hsum[(size_t)NB * NCH * LL];
__device__ int   g_hcnt[(size_t)NB * NCH * LL];
__device__ int   g_sidx[(size_t)NB * NCH * LL * CAPC];
__device__ float g_sval[(size_t)NB * NCH * LL * CAPC];
__device__ float g_m1max[(size_t)NB * NSC * LL];
__device__ float g_m1sum[(size_t)NB * NSC * LL];
__device__ int   g_ccnt[NB * LL];
__device__ int   g_cidx[(size_t)NB * LL * CAPF];
__device__ float g_cval[(size_t)NB * LL * CAPF];
__device__ float g_rinv[NB * LL];
__device__ float g_wmat[(size_t)NB * LL * ND];
__device__ float g_v[(size_t)NB * LL * ND];

// ---------------- small kernels ----------------------------------------------
__global__ void k_downsample(const float* __restrict__ f, const float* __restrict__ b) {
    int idx = blockIdx.x * 256 + threadIdx.x;           // NB*CC*64*64
    int j = idx & 63, i = (idx >> 6) & 63;
    int c = (idx >> 12) & 127, bb = idx >> 19;
    size_t src = ((size_t)(bb * CC + c) * 128 + 2 * i) * 128 + 2 * j;
    g_fds[idx] = f[src];
    g_bds[idx] = b[src];
}

__global__ void k_stats() {                              // S[b][l] = sum_c bds^2
    int idx = blockIdx.x * 256 + threadIdx.x;            // NB*LL
    int bb = idx >> 12; int l = idx & 4095;
    float acc = 0.f;
    for (int c = 0; c < CC; c++) {
        float v = g_bds[((size_t)bb * CC + c) * LL + l];
        acc = fmaf(v, v, acc);
    }
    g_S[idx] = acc;
}

__global__ void k_normmm(const float* __restrict__ mask) {
    int idx = blockIdx.x * 256 + threadIdx.x;            // NB*LL
    int bb = idx >> 12; int l = idx & 4095;
    int i = l >> 6, j = l & 63;
    float acc = 0.1152f;                                 // 1152 * 1e-4
    float msum = 0.f;
    for (int du = -1; du <= 1; du++)
        for (int dv = -1; dv <= 1; dv++) {
            int ii = i + du, jj = j + dv;
            if (ii >= 0 && ii < 64 && jj >= 0 && jj < 64) {
                acc += g_S[bb * LL + ii * 64 + jj];
                if (bb == 0) msum += mask[(2 * ii) * 128 + 2 * jj];
            }
        }
    g_inorm[idx] = rsqrtf(acc);
    if (bb == 0) g_mm[l] = (msum == 0.f) ? 1.f : 0.f;
}

// ---------------- packed f32x2 SGEMM (Gram): G[l][p] = sum_c bds[c][l]*fds[c][p]
#define BM 128
#define BN 128
#define BKK 16

__device__ __forceinline__ unsigned long long dup2(float x) {
    unsigned long long r;
    asm("mov.b64 %0, {%1, %2};" : "=l"(r) : "f"(x), "f"(x));
    return r;
}
__device__ __forceinline__ void ffma2(unsigned long long& d, unsigned long long a, unsigned long long b) {
    asm("fma.rn.f32x2 %0, %1, %2, %0;" : "+l"(d) : "l"(a), "l"(b));
}

__global__ __launch_bounds__(256, 2)
void gemm_gram() {
    const int M = LL, N = LL, K = CC;
    const float* A = g_bds; const float* Bm = g_fds; float* Cm = g_bufA;
    __shared__ float As[BKK][BM];
    __shared__ float Bs[BKK][BN];
    const int tid = threadIdx.x;
    const int m0 = blockIdx.y * BM, n0 = blockIdx.x * BN;
    const int z = blockIdx.z;
    A += (size_t)z * CC * LL; Bm += (size_t)z * CC * LL; Cm += (size_t)z * LL * LL;

    int lk[2], lm4[2];
#pragma unroll
    for (int r = 0; r < 2; r++) {
        int idx = tid + r * 256;
        lk[r] = idx >> 5;
        lm4[r] = (idx & 31) << 2;
    }

    unsigned long long acc[4][8];
#pragma unroll
    for (int a = 0; a < 4; a++)
#pragma unroll
        for (int b = 0; b < 8; b++) acc[a][b] = 0ull;

    const int ty = tid >> 4, tx = tid & 15;

    for (int k0 = 0; k0 < K; k0 += BKK) {
#pragma unroll
        for (int r = 0; r < 2; r++) {
            *(float4*)&As[lk[r]][lm4[r]] = *(const float4*)&A[(size_t)(k0 + lk[r]) * M + m0 + lm4[r]];
            *(float4*)&Bs[lk[r]][lm4[r]] = *(const float4*)&Bm[(size_t)(k0 + lk[r]) * N + n0 + lm4[r]];
        }
        __syncthreads();
#pragma unroll
        for (int kk = 0; kk < BKK; kk++) {
            const ulonglong2* A2 = (const ulonglong2*)&As[kk][0];
            ulonglong2 av0 = A2[ty];
            ulonglong2 av1 = A2[16 + ty];
            unsigned long long ap[4] = {av0.x, av0.y, av1.x, av1.y};
            const float4* B4 = (const float4*)&Bs[kk][0];
            float4 bv0 = B4[tx], bv1 = B4[16 + tx];
            unsigned long long bd[8] = {dup2(bv0.x), dup2(bv0.y), dup2(bv0.z), dup2(bv0.w),
                                        dup2(bv1.x), dup2(bv1.y), dup2(bv1.z), dup2(bv1.w)};
#pragma unroll
            for (int a = 0; a < 4; a++)
#pragma unroll
                for (int bj = 0; bj < 8; bj++) ffma2(acc[a][bj], ap[a], bd[bj]);
        }
        __syncthreads();
    }

    union UF { unsigned long long u; float2 f; };
#pragma unroll
    for (int a = 0; a < 4; a++) {
        int mrow = m0 + ((a & 2) ? 64 : 0) + ty * 4 + (a & 1) * 2;
        UF u0, u1, u2, u3;
        u0.u = acc[a][0]; u1.u = acc[a][1]; u2.u = acc[a][2]; u3.u = acc[a][3];
        float4 lo0 = make_float4(u0.f.x, u1.f.x, u2.f.x, u3.f.x);
        float4 hi0 = make_float4(u0.f.y, u1.f.y, u2.f.y, u3.f.y);
        u0.u = acc[a][4]; u1.u = acc[a][5]; u2.u = acc[a][6]; u3.u = acc[a][7];
        float4 lo1 = make_float4(u0.f.x, u1.f.x, u2.f.x, u3.f.x);
        float4 hi1 = make_float4(u0.f.y, u1.f.y, u2.f.y, u3.f.y);
        float* c0 = &Cm[(size_t)mrow * N + n0 + tx * 4];
        *(float4*)c0 = lo0;
        *(float4*)(c0 + 64) = lo1;
        float* c1 = &Cm[(size_t)(mrow + 1) * N + n0 + tx * 4];
        *(float4*)c1 = hi0;
        *(float4*)(c1 + 64) = hi1;
    }
}

// -------- diagonal-shift sum of Gram + normalization: G(bufA) -> y(bufB) -----
__global__ void k_diagsum() {
    int q = blockIdx.y * 256 + threadIdx.x;
    int r0 = blockIdx.x * LCH;
    int bb = blockIdx.z;
    int pi = q >> 6, pj = q & 63;
    const float* G = g_bufA + (size_t)bb * LL * LL;
    float* Y = g_bufB + (size_t)bb * LL * LL;
    bool qok[3][3]; int qoff[3][3];
#pragma unroll
    for (int du = -1; du <= 1; du++)
#pragma unroll
        for (int dv = -1; dv <= 1; dv++) {
            qok[du + 1][dv + 1] = ((unsigned)(pi + du) < 64u && (unsigned)(pj + dv) < 64u);
            qoff[du + 1][dv + 1] = q + du * 64 + dv;
        }
    for (int rr = 0; rr < LCH; rr++) {
        int r = r0 + rr;
        int i = r >> 6, j = r & 63;
        float acc = 0.f;
#pragma unroll
        for (int du = -1; du <= 1; du++)
#pragma unroll
            for (int dv = -1; dv <= 1; dv++) {
                if (qok[du + 1][dv + 1] &&
                    (unsigned)(i + du) < 64u && (unsigned)(j + dv) < 64u)
                    acc += G[(size_t)(r + du * 64 + dv) * LL + qoff[du + 1][dv + 1]];
            }
        Y[(size_t)r * LL + q] = acc * g_inorm[bb * LL + r];
    }
}

// -------- fused fuse1+fuse2 stencil -> logits in regs -> chunk select --------
__device__ __forceinline__ int Tsw(int x) { return ((x & 63) << 6) | (x >> 6); }

__global__ void k_logsel() {
    int p = blockIdx.y * 256 + threadIdx.x;
    int l0 = blockIdx.x * LCH;
    int bb = blockIdx.z;
    const float* Y = g_bufB + (size_t)bb * LL * LL;
    int q2 = Tsw(p);
    bool cok[3]; int cbase[3];
#pragma unroll
    for (int d2 = -1; d2 <= 1; d2++) {
        int qq = q2 + d2;
        cok[d2 + 1] = ((unsigned)qq < (unsigned)LL);
        cbase[d2 + 1] = cok[d2 + 1] ? Tsw(qq) : 0;
    }
    float lg[LCH];
    float mx = -1e30f;
#pragma unroll 4
    for (int ll = 0; ll < LCH; ll++) {
        int l = l0 + ll;
        int r2 = Tsw(l);
        float acc = 0.f;
#pragma unroll
        for (int d2 = -1; d2 <= 1; d2++) {
            int rr = r2 + d2;
            if (!cok[d2 + 1] || (unsigned)rr >= (unsigned)LL) continue;
            int a2 = Tsw(rr);
            int b2 = cbase[d2 + 1];
#pragma unroll
            for (int d1 = -1; d1 <= 1; d1++) {
                int aa = a2 + d1, bq = b2 + d1;
                if ((unsigned)aa < (unsigned)LL && (unsigned)bq < (unsigned)LL)
                    acc += Y[(size_t)aa * LL + bq];
            }
        }
        float v = acc * (g_mm[l] * 10.f);
        lg[ll] = v;
        mx = fmaxf(mx, v);
    }
    size_t hidx = ((size_t)bb * NCH + blockIdx.x) * LL + p;
    float s = 0.f;
    int cnt = 0;
    size_t base = hidx * CAPC;
    float thr = mx - 25.f;
#pragma unroll 4
    for (int ll = 0; ll < LCH; ll++) {
        float e = __expf(lg[ll] - mx);
        s += e;
        if (lg[ll] > thr && g_mm[l0 + ll] > 0.f) {
            g_sidx[base + cnt] = l0 + ll;
            g_sval[base + cnt] = e;
            cnt++;
        }
    }
    g_hmax[hidx] = mx;
    g_hsum[hidx] = s;
    g_hcnt[hidx] = cnt;
}

// -------- parallel superchunk reduction: max + rebased partial sums ----------
__global__ void k_gmax1() {
    int p = blockIdx.x * 256 + threadIdx.x;
    int sc = blockIdx.y;
    int bb = blockIdx.z;
    int c0 = sc * (NCH / NSC);
    float smax = -1e30f;
#pragma unroll 4
    for (int c = c0; c < c0 + NCH / NSC; c++)
        smax = fmaxf(smax, g_hmax[((size_t)bb * NCH + c) * LL + p]);
    float s = 0.f;
#pragma unroll 4
    for (int c = c0; c < c0 + NCH / NSC; c++) {
        size_t hidx = ((size_t)bb * NCH + c) * LL + p;
        s += g_hsum[hidx] * __expf(g_hmax[hidx] - smax);
    }
    size_t midx = ((size_t)bb * NSC + sc) * LL + p;
    g_m1max[midx] = smax;
    g_m1sum[midx] = s;
}

// -------- final merge with GLOBAL threshold (no intermediate truncation) -----
__global__ void k_mergef() {
    int p = blockIdx.x * 256 + threadIdx.x;
    int bb = blockIdx.y;
    float gmax = -1e30f;
#pragma unroll
    for (int sc = 0; sc < NSC; sc++)
        gmax = fmaxf(gmax, g_m1max[((size_t)bb * NSC + sc) * LL + p]);
    float s = 0.f;
#pragma unroll
    for (int sc = 0; sc < NSC; sc++) {
        size_t midx = ((size_t)bb * NSC + sc) * LL + p;
        s += g_m1sum[midx] * __expf(g_m1max[midx] - gmax);
    }
    float thr = gmax - 25.f;
    int cnt = 0;
    size_t cbase = (size_t)(bb * LL + p) * CAPF;
    for (int sc = 0; sc < NSC; sc++) {
        if (g_m1max[((size_t)bb * NSC + sc) * LL + p] <= thr) continue;
        int c0 = sc * (NCH / NSC);
        for (int c = c0; c < c0 + NCH / NSC; c++) {
            size_t hidx = ((size_t)bb * NCH + c) * LL + p;
            float hm = g_hmax[hidx];
            if (hm <= thr) continue;
            float scale = __expf(hm - gmax);
            int hc = g_hcnt[hidx];
            size_t ebase = hidx * CAPC;
            for (int i = 0; i < hc && cnt < CAPF; i++) {
                g_cidx[cbase + cnt] = g_sidx[ebase + i];
                g_cval[cbase + cnt] = g_sval[ebase + i] * scale;
                cnt++;
            }
        }
    }
    g_ccnt[bb * LL + p] = cnt;
    g_rinv[bb * LL + p] = 1.f / s;
}

// -------- pack raw 4x4 patches of b: W[b][l][c*16+kh*4+kw] -------------------
__global__ void k_packw(const float* __restrict__ b) {
    int idx = blockIdx.x * 256 + threadIdx.x;            // NB*LL*ND
    int n = idx & 2047, l = (idx >> 11) & 4095, bb = idx >> 23;
    int kw = n & 3, kh = (n >> 2) & 3, c = n >> 4;
    int li = l >> 6, lj = l & 63;
    int row = 2 * li - 1 + kh, col = 2 * lj - 1 + kw;
    float v = 0.f;
    if ((unsigned)row < 128u && (unsigned)col < 128u)
        v = b[((size_t)(bb * CC + c) * 128 + row) * 128 + col];
    g_wmat[idx] = v;
}

// -------- sparse attn @ W: g_v[p][n] = sum_{selected l} e * W[l][n] ----------
__global__ __launch_bounds__(256, 4)
void k_spmm() {
    int p = blockIdx.x, bb = blockIdx.y;
    int tid = threadIdx.x;
    int cnt = g_ccnt[bb * LL + p];
    size_t base = (size_t)(bb * LL + p) * CAPF;
    const float* W = g_wmat + (size_t)bb * LL * ND;
    float4 a0 = make_float4(0.f, 0.f, 0.f, 0.f);
    float4 a1 = make_float4(0.f, 0.f, 0.f, 0.f);
    for (int i = 0; i < cnt; i++) {
        int l = g_cidx[base + i];
        float e = g_cval[base + i];
        const float4* w = (const float4*)(W + (size_t)l * ND);
        float4 w0 = w[tid], w1 = w[tid + 256];
        a0.x = fmaf(e, w0.x, a0.x); a0.y = fmaf(e, w0.y, a0.y);
        a0.z = fmaf(e, w0.z, a0.z); a0.w = fmaf(e, w0.w, a0.w);
        a1.x = fmaf(e, w1.x, a1.x); a1.y = fmaf(e, w1.y, a1.y);
        a1.z = fmaf(e, w1.z, a1.z); a1.w = fmaf(e, w1.w, a1.w);
    }
    float4* out = (float4*)(g_v + (size_t)(bb * LL + p) * ND);
    out[tid] = a0;
    out[tid + 256] = a1;
}

// -------- smem-staged gather over oh-quads: rinv & /4 folded -----------------
__global__ __launch_bounds__(256, 4)
void k_gather(float* __restrict__ out) {
    __shared__ float sm[512][17];                        // [(cl*4+ihsel)*64+iw][k]
    int cpair = blockIdx.x;                              // 0..63
    int oh0 = blockIdx.y * OHB;
    int bb = blockIdx.z;
    int tid = threadIdx.x;
    const float* P = g_v + (size_t)bb * LL * ND;
    const float* rin = g_rinv + bb * LL;
    int ihb = (oh0 >> 1) - 1;                            // ih base (4 rows: ihb..ihb+3)

#pragma unroll
    for (int rseg = 0; rseg < 2; rseg++) {
        int seg = tid + rseg * 256;
        int cl = seg >> 8;
        int rem = seg & 255;
        int ihsel = rem >> 6, iw = rem & 63;
        int ih = ihb + ihsel;
        int c = cpair * 2 + cl;
        if ((unsigned)ih < 64u) {
            int pp = ih * 64 + iw;
            float rv = rin[pp];
            const float4* src = (const float4*)(P + (size_t)pp * ND + c * 16);
#pragma unroll
            for (int v4 = 0; v4 < 4; v4++) {
                float4 w = src[v4];
                sm[seg][v4 * 4 + 0] = w.x * rv;
                sm[seg][v4 * 4 + 1] = w.y * rv;
                sm[seg][v4 * 4 + 2] = w.z * rv;
                sm[seg][v4 * 4 + 3] = w.w * rv;
            }
        } else {
#pragma unroll
            for (int k = 0; k < 16; k++) sm[seg][k] = 0.f;
        }
    }
    __syncthreads();

    int cl = tid >> 7;
    int ow = tid & 127;
    int c = cpair * 2 + cl;
    int q0 = (ow + 1) & 1;
    int iwH = (ow + 1 - q0) >> 1;                        // kw = q0
    int iwL = iwH - 1;                                   // kw = q0+2
#pragma unroll
    for (int dh = 0; dh < OHB; dh++) {
        int oh = oh0 + dh;
        int p0 = (oh + 1) & 1;
        int ih_hi = (oh + 1 - p0) >> 1;
        float acc = 0.f;
#pragma unroll
        for (int a = 0; a < 2; a++) {
            int kh = p0 + 2 * a;
            int ihsel = (ih_hi - a) - ihb;               // in [0,4)
#pragma unroll
            for (int bq = 0; bq < 2; bq++) {
                int kw = q0 + 2 * bq;
                int iw = bq ? iwL : iwH;
                if ((unsigned)iw < 64u)
                    acc += sm[(cl * 4 + ihsel) * 64 + iw][kh * 4 + kw];
            }
        }
        out[(((size_t)bb * CC + c) * 128 + oh) * 128 + ow] = acc * 0.25f;
    }
}

// ---------------- launch -----------------------------------------------------
extern "C" void kernel_launch(void* const* d_in, const int* in_sizes, int n_in,
                              void* d_out, int out_size) {
    const float* f = (const float*)d_in[0];
    const float* b = (const float*)d_in[1];
    const float* mask = (const float*)d_in[2];
    float* out = (float*)d_out;

    k_downsample<<<4096, 256>>>(f, b);
    k_stats<<<32, 256>>>();
    k_normmm<<<32, 256>>>(mask);
    gemm_gram<<<dim3(32, 32, NB), 256>>>();
    k_diagsum<<<dim3(NCH, 16, NB), 256>>>();
    k_logsel<<<dim3(NCH, 16, NB), 256>>>();
    k_gmax1<<<dim3(16, NSC, NB), 256>>>();
    k_mergef<<<dim3(16, NB), 256>>>();
    k_packw<<<65536, 256>>>(b);
    k_spmm<<<dim3(4096, NB), 256>>>();
    k_gather<<<dim3(64, 128 / OHB, NB), 256>>>(out);
}